// round 6
// baseline (speedup 1.0000x reference)
#include <cuda_runtime.h>
#include <cstdint>

#define N_NODES 4096
#define K_TOT   16384
#define DIN     64
#define OUT64   64

#define TILE_M  128
#define KC      64
#define SPLIT   16
#define KSPAN   (K_TOT / SPLIT)   // 1024
#define NCH     (KSPAN / KC)      // 16
#define NCHUNKS (K_TOT / KC)      // 256

// B digit planes, packed s8x4 words, fragment-interleaved:
// g_B1[ck][o][pos] ; word w = n&15 holds bytes c=0..3 for node n = ck*16 + w
__device__ uint32_t g_B1[NCHUNKS * 64 * 16];
__device__ uint32_t g_B2[NCHUNKS * 64 * 16];
// split-K partials
__device__ float g_part[(size_t)SPLIT * N_NODES * OUT64];

// ---------------------------------------------------------------------------
__device__ __forceinline__ uint32_t smem_u32(const void* p) {
    uint32_t a;
    asm("{ .reg .u64 t; cvta.to.shared.u64 t, %1; cvt.u32.u64 %0, t; }"
        : "=r"(a) : "l"(p));
    return a;
}

#define CP_ASYNC16(dst, src) \
    asm volatile("cp.async.cg.shared.global [%0], [%1], 16;" :: "r"(dst), "l"(src))
#define CP_COMMIT() asm volatile("cp.async.commit_group;" ::: "memory")
#define CP_WAIT0()  asm volatile("cp.async.wait_group 0;" ::: "memory")

#define LDS64(r0, r1, addr) \
    asm volatile("ld.shared.v2.b32 {%0,%1}, [%2];" : "=r"(r0), "=r"(r1) : "r"(addr))

#define MMA_S8(d, a, b0, b1) \
    asm volatile("mma.sync.aligned.m16n8k32.row.col.s32.s8.s8.s32 " \
        "{%0,%1,%2,%3}, {%4,%5,%6,%7}, {%8,%9}, {%0,%1,%2,%3};" \
        : "+r"((d)[0]), "+r"((d)[1]), "+r"((d)[2]), "+r"((d)[3]) \
        : "r"((a)[0]), "r"((a)[1]), "r"((a)[2]), "r"((a)[3]), "r"(b0), "r"(b1))

// smem per buffer: plane1 (64 rows x 80B) + plane2
#define PLANE  5120u
#define BBUF   10240u

// ---------------------------------------------------------------------------
// build_B: support = circular-conv(features, weight); emit int8 digit planes.
// 256 blocks x 256 threads, 16 nodes per block.
// ---------------------------------------------------------------------------
__global__ void __launch_bounds__(256) build_B_kernel(
    const float* __restrict__ features,   // [N, DIN, 4]
    const float* __restrict__ weight)     // [DIN, 16, 4]
{
    __shared__ float s_w[DIN * OUT64];          // [j][r*4+e] 16KB
    __shared__ float s_f[4 * DIN * 4];          // 4 nodes x 256
    __shared__ float s_frot[4][4][DIN * 4];     // [node][k][j*4+e] 16KB

    const int tid  = threadIdx.x;
    const int lane = tid & 31;
    const int ln   = tid >> 6;             // local node 0..3
    const int o    = tid & 63;
    const int r    = o >> 2;
    const int k    = o & 3;

    #pragma unroll
    for (int i = 0; i < 4; i++)
        ((float4*)s_w)[tid + i * 256] = ((const float4*)weight)[tid + i * 256];

    for (int ng = 0; ng < 4; ng++) {
        __syncthreads();
        const int nb = blockIdx.x * 16 + ng * 4;
        ((float4*)s_f)[tid] = ((const float4*)(features + (size_t)nb * 256))[tid];
        __syncthreads();

        // pre-rotated f: s_frot[nn][kk][j*4+e] = f[nn][j*4 + ((kk-e)&3)]
        #pragma unroll
        for (int ii = 0; ii < 16; ii++) {
            int e   = tid + ii * 256;
            int nn  = e >> 10;
            int kk  = (e >> 8) & 3;
            int jc  = e & 255;
            int c2  = jc & 3;
            s_frot[nn][kk][jc] = s_f[nn * 256 + (jc & ~3) + ((kk - c2) & 3)];
        }
        __syncthreads();

        float a0 = 0.f, a1 = 0.f, a2 = 0.f, a3 = 0.f;
        const float4* fr = (const float4*)&s_frot[ln][k][0];
        #pragma unroll 16
        for (int j = 0; j < DIN; j++) {
            float4 f4 = fr[j];
            float4 w4 = *(const float4*)&s_w[j * 64 + r * 4];
            a0 = fmaf(f4.x, w4.x, a0);
            a1 = fmaf(f4.y, w4.y, a1);
            a2 = fmaf(f4.z, w4.z, a2);
            a3 = fmaf(f4.w, w4.w, a3);
        }
        const float acc = (a0 + a1) + (a2 + a3);   // sup[n, r, k]

        // gather the 4 channel shifts, quantize to 2 s8 digits, pack
        // b = B1/8 + B2/1024  (|sup| < 15.9 representable; clip p ~ 1e-6)
        uint32_t p1 = 0, p2 = 0;
        #pragma unroll
        for (int c = 0; c < 4; c++) {
            float v = __shfl_sync(0xffffffffu, acc, (lane & ~3) | ((k - c) & 3));
            int b1 = __float2int_rn(v * 8.f);
            b1 = max(-127, min(127, b1));
            float rr = v - (float)b1 * 0.125f;
            int b2 = __float2int_rn(rr * 1024.f);
            b2 = max(-127, min(127, b2));
            p1 |= ((uint32_t)b1 & 0xFFu) << (8 * c);
            p2 |= ((uint32_t)b2 & 0xFFu) << (8 * c);
        }
        const int n = nb + ln;
        const int w = n & 15;
        const int pos = (w & 8) | (((w & 3) << 1) + ((w >> 2) & 1));
        const int idx = (((n >> 4) * 64) + o) * 16 + pos;
        g_B1[idx] = p1;
        g_B2[idx] = p2;
    }
}

// ---------------------------------------------------------------------------
// B chunk loader: both digit planes, 64 rows x 64B -> 80B-pitch smem
// ---------------------------------------------------------------------------
__device__ __forceinline__ void loadB(uint32_t dst, int ck, int tid)
{
    const int row = tid >> 2, seg = tid & 3;
    const char* s1 = (const char*)(g_B1 + (size_t)ck * 1024 + row * 16 + seg * 4);
    const char* s2 = (const char*)(g_B2 + (size_t)ck * 1024 + row * 16 + seg * 4);
    uint32_t d = dst + (uint32_t)row * 80u + (uint32_t)seg * 16u;
    CP_ASYNC16(d, s1);
    CP_ASYNC16(d + PLANE, s2);
}

// quantize float4 -> packed digit bytes (A1: bits 13..7, A2: bits 6..0)
__device__ __forceinline__ void q4(float4 v, uint32_t& p1, uint32_t& p2)
{
    uint32_t q0 = __float_as_uint(fmaf(v.x, 16384.f, 8388608.f)) & 0xFFFFu;
    uint32_t q1 = __float_as_uint(fmaf(v.y, 16384.f, 8388608.f)) & 0xFFFFu;
    uint32_t q2 = __float_as_uint(fmaf(v.z, 16384.f, 8388608.f)) & 0xFFFFu;
    uint32_t q3 = __float_as_uint(fmaf(v.w, 16384.f, 8388608.f)) & 0xFFFFu;
    q0 = min(q0, 16383u); q1 = min(q1, 16383u);
    q2 = min(q2, 16383u); q3 = min(q3, 16383u);
    p1 = (q0 >> 7) | ((q1 >> 7) << 8) | ((q2 >> 7) << 16) | ((q3 >> 7) << 24);
    p2 = (q0 & 127u) | ((q1 & 127u) << 8) | ((q2 & 127u) << 16) | ((q3 & 127u) << 24);
}

// ---------------------------------------------------------------------------
// GEMM: partial[i][o] = sum_k adj[i][k]*Bt[o][k] via int8 mma m16n8k32.
// out = S11/1024 + (S12+S21)/131072, exact s32 accumulation.
// Warp tile 16 rows x 64 cols; grid (32, 16), 256 threads.
// ---------------------------------------------------------------------------
__global__ void __launch_bounds__(256, 2) gemm_mma(const float* __restrict__ adj)
{
    __shared__ uint32_t sBm[2 * BBUF / 4];
    const uint32_t base = smem_u32(sBm);

    const int tid  = threadIdx.x;
    const int wid  = tid >> 5;
    const int lane = tid & 31;
    const int g    = lane >> 2;
    const int t    = lane & 3;
    const int i0   = blockIdx.x * TILE_M;
    const int kbase = blockIdx.y * KSPAN;
    const int ck0   = blockIdx.y * NCH;

    int acc1[8][4], accX[8][4];
    #pragma unroll
    for (int nt = 0; nt < 8; nt++)
        #pragma unroll
        for (int q = 0; q < 4; q++) { acc1[nt][q] = 0; accX[nt][q] = 0; }

    // this thread's A rows: g and g+8 of the warp's 16-row tile
    const float* ap = adj + (size_t)(i0 + wid * 16 + g) * K_TOT + kbase + t * 4;

    loadB(base, ck0, tid);
    CP_COMMIT();

    for (int s = 0; s < NCH; s++) {
        CP_WAIT0();
        __syncthreads();
        if (s + 1 < NCH) {
            loadB(base + (uint32_t)((s + 1) & 1) * BBUF, ck0 + s + 1, tid);
            CP_COMMIT();
        }
        const uint32_t sb = base + (uint32_t)(s & 1) * BBUF;

        #pragma unroll
        for (int ks = 0; ks < 2; ks++) {
            const float* a0p = ap + s * 64 + ks * 32;
            float4 v00 = *(const float4*)(a0p);                     // row g,   k-lo
            float4 v10 = *(const float4*)(a0p + 8 * K_TOT);         // row g+8, k-lo
            float4 v01 = *(const float4*)(a0p + 16);                // row g,   k-hi
            float4 v11 = *(const float4*)(a0p + 8 * K_TOT + 16);    // row g+8, k-hi

            uint32_t fA1[4], fA2[4];
            q4(v00, fA1[0], fA2[0]);
            q4(v10, fA1[1], fA2[1]);
            q4(v01, fA1[2], fA2[2]);
            q4(v11, fA1[3], fA2[3]);

            const uint32_t wordoff = (uint32_t)(ks * 8 + 2 * t) * 4u;
            #pragma unroll
            for (int nt = 0; nt < 8; nt++) {
                uint32_t addr = sb + (uint32_t)(nt * 8 + g) * 80u + wordoff;
                uint32_t b1a, b1b, b2a, b2b;
                LDS64(b1a, b1b, addr);
                LDS64(b2a, b2b, addr + PLANE);
                MMA_S8(acc1[nt], fA1, b1a, b1b);   // A1*B1
                MMA_S8(accX[nt], fA1, b2a, b2b);   // A1*B2
                MMA_S8(accX[nt], fA2, b1a, b1b);   // A2*B1
            }
        }
    }

    // epilogue: partial = S11/1024 + SX/131072
    const float c1 = 1.f / 1024.f;
    const float c2 = 1.f / 131072.f;
    float* p = g_part + (size_t)blockIdx.y * (N_NODES * OUT64);
    const int r0 = i0 + wid * 16 + g;
    #pragma unroll
    for (int nt = 0; nt < 8; nt++) {
        const int c0 = nt * 8 + 2 * t;
        float f0 = (float)acc1[nt][0] * c1 + (float)accX[nt][0] * c2;
        float f1 = (float)acc1[nt][1] * c1 + (float)accX[nt][1] * c2;
        float f2 = (float)acc1[nt][2] * c1 + (float)accX[nt][2] * c2;
        float f3 = (float)acc1[nt][3] * c1 + (float)accX[nt][3] * c2;
        *(float2*)&p[(size_t)r0 * 64 + c0]       = make_float2(f0, f1);
        *(float2*)&p[(size_t)(r0 + 8) * 64 + c0] = make_float2(f2, f3);
    }
}

// ---------------------------------------------------------------------------
// Reduce: out = bias + sum over SPLIT partials
// ---------------------------------------------------------------------------
__global__ void __launch_bounds__(256) reduce_k(
    const float* __restrict__ bias, float* __restrict__ out)
{
    const int idx = blockIdx.x * 256 + threadIdx.x;
    float4 s = ((const float4*)bias)[idx];
    #pragma unroll
    for (int tt = 0; tt < SPLIT; tt++) {
        float4 q = *(const float4*)&g_part[(size_t)tt * (N_NODES * OUT64) + (size_t)idx * 4];
        s.x += q.x; s.y += q.y; s.z += q.z; s.w += q.w;
    }
    ((float4*)out)[idx] = s;
}

// ---------------------------------------------------------------------------
extern "C" void kernel_launch(void* const* d_in, const int* in_sizes, int n_in,
                              void* d_out, int out_size)
{
    const float* features = (const float*)d_in[0];
    const float* adj      = (const float*)d_in[1];
    const float* weight   = (const float*)d_in[2];
    const float* bias     = (const float*)d_in[3];
    float* out            = (float*)d_out;
    (void)in_sizes; (void)n_in; (void)out_size;

    build_B_kernel<<<256, 256>>>(features, weight);
    gemm_mma<<<dim3(N_NODES / TILE_M, SPLIT), 256>>>(adj);
    reduce_k<<<(N_NODES * OUT64 / 4) / 256, 256>>>(bias, out);
}

// round 7
// speedup vs baseline: 2.8491x; 2.8491x over previous
#include <cuda_runtime.h>
#include <cuda_fp16.h>
#include <cstdint>

#define N_NODES 4096
#define K_TOT   16384
#define DIN     64
#define OUT64   64

#define TILE_M  128
#define KC      64
#define SPLIT   16
#define KSPAN   (K_TOT / SPLIT)   // 1024
#define NCH     (KSPAN / KC)      // 16

// B^T in fp16: g_B[o][k], 64 x 16384 row-major (o = r*4+k_ch)
__device__ unsigned short g_B[64 * K_TOT];
// split-K partials
__device__ float g_part[(size_t)SPLIT * N_NODES * OUT64];

// ---------------------------------------------------------------------------
__device__ __forceinline__ uint32_t smem_u32(const void* p) {
    uint32_t a;
    asm("{ .reg .u64 t; cvta.to.shared.u64 t, %1; cvt.u32.u64 %0, t; }"
        : "=r"(a) : "l"(p));
    return a;
}

#define CP_ASYNC16(dst, src) \
    asm volatile("cp.async.cg.shared.global [%0], [%1], 16;" :: "r"(dst), "l"(src))
#define CP_COMMIT() asm volatile("cp.async.commit_group;" ::: "memory")
#define CP_WAIT0()  asm volatile("cp.async.wait_group 0;" ::: "memory")

#define LDSM_X4(r, addr) \
    asm volatile("ldmatrix.sync.aligned.m8n8.x4.shared.b16 {%0,%1,%2,%3}, [%4];" \
        : "=r"((r)[0]), "=r"((r)[1]), "=r"((r)[2]), "=r"((r)[3]) : "r"(addr))

#define MMA_F16(d, a, b0, b1) \
    asm volatile("mma.sync.aligned.m16n8k16.row.col.f32.f16.f16.f32 " \
        "{%0,%1,%2,%3}, {%4,%5,%6,%7}, {%8,%9}, {%0,%1,%2,%3};" \
        : "+f"((d)[0]), "+f"((d)[1]), "+f"((d)[2]), "+f"((d)[3]) \
        : "r"((a)[0]), "r"((a)[1]), "r"((a)[2]), "r"((a)[3]), "r"(b0), "r"(b1))

// pack two f32 -> f16x2 (x in low half, y in high half)
#define F16X2(u, x, y) \
    asm("cvt.rn.f16x2.f32 %0, %1, %2;" : "=r"(u) : "f"(y), "f"(x))

// smem: B tile only, double-buffered: 64 rows x 144B pitch (holds 64 fp16 k)
#define BPITCH 144u
#define BBUF   9216u
// static smem: 2*9216 = 18432 B

// ---------------------------------------------------------------------------
// build_B: support = circular-conv(features, weight); emit fp16 B^T.
// grid 512, 8 nodes per block (round-4 structure, single output plane).
// ---------------------------------------------------------------------------
__global__ void __launch_bounds__(256) build_B_kernel(
    const float* __restrict__ features,   // [N, DIN, 4]
    const float* __restrict__ weight)     // [DIN, 16, 4]
{
    __shared__ float s_w[DIN * OUT64];     // 16KB
    __shared__ float s_f[4 * DIN * 4];     // 4 nodes x 256 floats

    const int tid  = threadIdx.x;
    const int lane = tid & 31;
    const int ln   = tid >> 6;             // local node 0..3
    const int o    = tid & 63;             // r*4+k
    const int r    = o >> 2;
    const int k    = o & 3;

    #pragma unroll
    for (int i = 0; i < 4; i++)
        ((float4*)s_w)[tid + i * 256] = ((const float4*)weight)[tid + i * 256];

    #pragma unroll
    for (int ng = 0; ng < 2; ng++) {
        __syncthreads();
        const int nb = blockIdx.x * 8 + ng * 4;
        ((float4*)s_f)[tid] = ((const float4*)(features + (size_t)nb * 256))[tid];
        __syncthreads();

        float acc = 0.f;
        const float* fp = s_f + ln * 256;
        #pragma unroll 8
        for (int j = 0; j < DIN; j++) {
            #pragma unroll
            for (int c = 0; c < 4; c++)
                acc += fp[j * 4 + c] * s_w[j * 64 + r * 4 + ((k - c) & 3)];
        }

        // gather the 4 channel shifts via intra-quad shuffle, pack fp16x4
        float v[4];
        #pragma unroll
        for (int c = 0; c < 4; c++)
            v[c] = __shfl_sync(0xffffffffu, acc, (lane & ~3) | ((k - c) & 3));
        uint32_t h01, h23;
        F16X2(h01, v[0], v[1]);
        F16X2(h23, v[2], v[3]);

        const int n = nb + ln;
        size_t off = (size_t)o * K_TOT + (size_t)n * 4;
        *(uint2*)(&g_B[off]) = make_uint2(h01, h23);
    }
}

// ---------------------------------------------------------------------------
// B tile loader: fp16 [64 o-rows x 64 k], 144B-pitch smem
// ---------------------------------------------------------------------------
__device__ __forceinline__ void loadB(uint32_t dst, int kk0, int tid)
{
    #pragma unroll
    for (int i = 0; i < 2; i++) {
        int e = tid + i * 256;
        int row = e >> 3, seg = e & 7;
        uint32_t d = dst + (uint32_t)row * BPITCH + (uint32_t)seg * 16u;
        const char* s = (const char*)g_B + ((size_t)row * K_TOT + kk0) * 2 + seg * 16;
        CP_ASYNC16(d, s);
    }
}

// ---------------------------------------------------------------------------
// GEMM: partial[i][o] = sum_k adj[i][k] * Bt[o][k], single fp16 term,
// fp32 accumulation in mma. Warp tile 16 rows x 64 cols; grid (32,16).
// ---------------------------------------------------------------------------
__global__ void __launch_bounds__(256, 2) gemm_mma(const float* __restrict__ adj)
{
    __shared__ __align__(16) char sB[2 * BBUF];
    const uint32_t base = smem_u32(sB);

    const int tid  = threadIdx.x;
    const int wid  = tid >> 5;
    const int lane = tid & 31;
    const int g    = lane >> 2;
    const int t    = lane & 3;
    const int i0    = blockIdx.x * TILE_M;
    const int kbase = blockIdx.y * KSPAN;

    float acc[8][4];
    #pragma unroll
    for (int nt = 0; nt < 8; nt++)
        #pragma unroll
        for (int q = 0; q < 4; q++) acc[nt][q] = 0.f;

    // this thread's A rows: g and g+8 of the warp's 16-row tile
    const float* ap = adj + (size_t)(i0 + wid * 16 + g) * K_TOT + kbase + 2 * t;

    loadB(base, kbase, tid);
    CP_COMMIT();

    const uint32_t lrow = (uint32_t)(lane & 15);
    const uint32_t lkb  = (uint32_t)(lane & 16);

    for (int s = 0; s < NCH; s++) {
        // batch all A loads for this chunk (MLP=16)
        float2 P[4][4];
        #pragma unroll
        for (int ks = 0; ks < 4; ks++) {
            const float* q0 = ap + s * 64 + ks * 16;
            P[ks][0] = *(const float2*)(q0);                   // row g,   k-lo
            P[ks][1] = *(const float2*)(q0 + 8 * K_TOT);       // row g+8, k-lo
            P[ks][2] = *(const float2*)(q0 + 8);               // row g,   k-hi
            P[ks][3] = *(const float2*)(q0 + 8 * K_TOT + 8);   // row g+8, k-hi
        }
        uint32_t af[4][4];
        #pragma unroll
        for (int ks = 0; ks < 4; ks++)
            #pragma unroll
            for (int m = 0; m < 4; m++)
                F16X2(af[ks][m], P[ks][m].x, P[ks][m].y);

        CP_WAIT0();
        __syncthreads();
        if (s + 1 < NCH) {
            loadB(base + (uint32_t)((s ^ 1) & 1) * BBUF, kbase + (s + 1) * KC, tid);
            CP_COMMIT();
        }
        const uint32_t sb = base + (uint32_t)(s & 1) * BBUF;

        #pragma unroll
        for (int ks = 0; ks < 4; ks++) {
            #pragma unroll
            for (int nt2 = 0; nt2 < 4; nt2++) {     // 16-o tiles
                uint32_t baddr = sb + (uint32_t)(nt2 * 16 + lrow) * BPITCH
                               + (uint32_t)(ks * 32) + lkb;
                uint32_t bb[4];
                LDSM_X4(bb, baddr);
                MMA_F16(acc[nt2 * 2],     af[ks], bb[0], bb[2]);
                MMA_F16(acc[nt2 * 2 + 1], af[ks], bb[1], bb[3]);
            }
        }
        __syncthreads();
    }

    // write split-K partials
    float* p = g_part + (size_t)blockIdx.y * (N_NODES * OUT64);
    const int r0 = i0 + wid * 16 + g;
    #pragma unroll
    for (int nt = 0; nt < 8; nt++) {
        const int c0 = nt * 8 + 2 * t;
        *(float2*)&p[(size_t)r0 * 64 + c0]       = make_float2(acc[nt][0], acc[nt][1]);
        *(float2*)&p[(size_t)(r0 + 8) * 64 + c0] = make_float2(acc[nt][2], acc[nt][3]);
    }
}

// ---------------------------------------------------------------------------
// Reduce: out = bias + sum over SPLIT partials
// ---------------------------------------------------------------------------
__global__ void __launch_bounds__(256) reduce_k(
    const float* __restrict__ bias, float* __restrict__ out)
{
    const int idx = blockIdx.x * 256 + threadIdx.x;
    float4 s = ((const float4*)bias)[idx];
    #pragma unroll
    for (int tt = 0; tt < SPLIT; tt++) {
        float4 q = *(const float4*)&g_part[(size_t)tt * (N_NODES * OUT64) + (size_t)idx * 4];
        s.x += q.x; s.y += q.y; s.z += q.z; s.w += q.w;
    }
    ((float4*)out)[idx] = s;
}

// ---------------------------------------------------------------------------
extern "C" void kernel_launch(void* const* d_in, const int* in_sizes, int n_in,
                              void* d_out, int out_size)
{
    const float* features = (const float*)d_in[0];
    const float* adj      = (const float*)d_in[1];
    const float* weight   = (const float*)d_in[2];
    const float* bias     = (const float*)d_in[3];
    float* out            = (float*)d_out;
    (void)in_sizes; (void)n_in; (void)out_size;

    build_B_kernel<<<512, 256>>>(features, weight);
    gemm_mma<<<dim3(N_NODES / TILE_M, SPLIT), 256>>>(adj);
    reduce_k<<<(N_NODES * OUT64 / 4) / 256, 256>>>(bias, out);
}

// round 8
// speedup vs baseline: 3.4377x; 1.2066x over previous
#include <cuda_runtime.h>
#include <cuda_fp16.h>
#include <cstdint>

#define N_NODES 4096
#define K_TOT   16384
#define OUT64   64

#define TILE_M  128
#define KC      64
#define SPLIT   16
#define KSPAN   (K_TOT / SPLIT)   // 1024
#define NCH     (KSPAN / KC)      // 16

// B^T in fp16: g_B[o][k], 64 x 16384 row-major (o = r*4+kch, k = n*4+c)
__device__ unsigned short g_B[64 * K_TOT];

// ---------------------------------------------------------------------------
__device__ __forceinline__ uint32_t smem_u32(const void* p) {
    uint32_t a;
    asm("{ .reg .u64 t; cvta.to.shared.u64 t, %1; cvt.u32.u64 %0, t; }"
        : "=r"(a) : "l"(p));
    return a;
}

#define CP_ASYNC16(dst, src) \
    asm volatile("cp.async.cg.shared.global [%0], [%1], 16;" :: "r"(dst), "l"(src))
#define CP_COMMIT() asm volatile("cp.async.commit_group;" ::: "memory")
#define CP_WAIT0()  asm volatile("cp.async.wait_group 0;" ::: "memory")

#define LDSM_X4(r, addr) \
    asm volatile("ldmatrix.sync.aligned.m8n8.x4.shared.b16 {%0,%1,%2,%3}, [%4];" \
        : "=r"((r)[0]), "=r"((r)[1]), "=r"((r)[2]), "=r"((r)[3]) : "r"(addr))

#define MMA_F16(d, a, b0, b1) \
    asm volatile("mma.sync.aligned.m16n8k16.row.col.f32.f16.f16.f32 " \
        "{%0,%1,%2,%3}, {%4,%5,%6,%7}, {%8,%9}, {%0,%1,%2,%3};" \
        : "+f"((d)[0]), "+f"((d)[1]), "+f"((d)[2]), "+f"((d)[3]) \
        : "r"((a)[0]), "r"((a)[1]), "r"((a)[2]), "r"((a)[3]), "r"(b0), "r"(b1))

// pack two f32 -> f16x2 (x in LOW half, y in HIGH half)
#define F16X2(u, x, y) \
    asm("cvt.rn.f16x2.f32 %0, %1, %2;" : "=r"(u) : "f"(y), "f"(x))

// ---------------------------------------------------------------------------
// build_gemm: g_B^T[n][(o,c)] = features[n,:] @ B2,
//   B2[(j,e)][m=(r,kk,c)] = w[j, r, (kk - c - e) & 3]   (fp16 MMA, K=256)
// grid (32 node-tiles x 4 m-slices), 256 threads (8 warps x 16 rows x 64 cols)
// ---------------------------------------------------------------------------
#define B2PITCH 528u

__global__ void __launch_bounds__(256) build_gemm(
    const float* __restrict__ features,   // [4096, 256] = [n][(j,e)]
    const float* __restrict__ weight)     // [64, 16, 4]  = [j][r][shift]
{
    __shared__ float s_w[4096];                          // 16KB
    __shared__ __align__(16) char s_b2[64 * B2PITCH];    // 33KB: B2^T slice

    const int tid  = threadIdx.x;
    const int wid  = tid >> 5;
    const int lane = tid & 31;
    const int g    = lane >> 2;
    const int t    = lane & 3;
    const int n0   = blockIdx.x * 128;
    const int m0   = blockIdx.y * 64;

    #pragma unroll
    for (int i = 0; i < 4; i++)
        ((float4*)s_w)[tid + i * 256] = ((const float4*)weight)[tid + i * 256];
    __syncthreads();

    // expand this block's B2^T slice: rows mloc (64), cols jc (256) fp16
    #pragma unroll
    for (int idx = tid; idx < 64 * 256; idx += 256) {
        const int mloc = idx >> 8, jc = idx & 255;
        const int m = m0 + mloc;
        const int r = m >> 4, kk = (m >> 2) & 3, c = m & 3;
        const int j = jc >> 2, e = jc & 3;
        const float val = s_w[j * 64 + r * 4 + ((kk - c - e) & 3)];
        *(unsigned short*)(s_b2 + mloc * B2PITCH + jc * 2) =
            __half_as_ushort(__float2half_rn(val));
    }
    __syncthreads();

    const uint32_t base = smem_u32(s_b2);
    const uint32_t lrow = (uint32_t)(lane & 15);
    const uint32_t lkb  = (uint32_t)(lane & 16);

    float acc[8][4];
    #pragma unroll
    for (int nt = 0; nt < 8; nt++)
        #pragma unroll
        for (int q = 0; q < 4; q++) acc[nt][q] = 0.f;

    const float* fp = features + (size_t)(n0 + wid * 16 + g) * 256 + 2 * t;

    #pragma unroll 4
    for (int ks = 0; ks < 16; ks++) {
        const float* q0 = fp + ks * 16;
        float2 p0 = *(const float2*)(q0);
        float2 p1 = *(const float2*)(q0 + 8 * 256);
        float2 p2 = *(const float2*)(q0 + 8);
        float2 p3 = *(const float2*)(q0 + 8 * 256 + 8);
        uint32_t af[4];
        F16X2(af[0], p0.x, p0.y);
        F16X2(af[1], p1.x, p1.y);
        F16X2(af[2], p2.x, p2.y);
        F16X2(af[3], p3.x, p3.y);

        #pragma unroll
        for (int nt2 = 0; nt2 < 4; nt2++) {
            uint32_t baddr = base + (uint32_t)(nt2 * 16 + lrow) * B2PITCH
                           + (uint32_t)(ks * 32) + lkb;
            uint32_t bb[4];
            LDSM_X4(bb, baddr);
            MMA_F16(acc[nt2 * 2],     af, bb[0], bb[2]);
            MMA_F16(acc[nt2 * 2 + 1], af, bb[1], bb[3]);
        }
    }

    // write fragments straight into g_B (each col-pair = aligned 4B f16x2)
    const int n = n0 + wid * 16 + g;
    #pragma unroll
    for (int nt = 0; nt < 8; nt++) {
        const int m = m0 + nt * 8 + 2 * t;
        const int o = m >> 2, c = m & 3;
        uint32_t lo, hi;
        F16X2(lo, acc[nt][0], acc[nt][1]);
        F16X2(hi, acc[nt][2], acc[nt][3]);
        *(uint32_t*)((char*)g_B + ((size_t)o * K_TOT + n * 4 + c) * 2)       = lo;
        *(uint32_t*)((char*)g_B + ((size_t)o * K_TOT + (n + 8) * 4 + c) * 2) = hi;
    }
}

// ---------------------------------------------------------------------------
// B tile loader for main gemm: fp16 [64 o-rows x 64 k], 144B-pitch smem
// ---------------------------------------------------------------------------
#define BPITCH 144u
#define BBUF   9216u

__device__ __forceinline__ void loadB(uint32_t dst, int kk0, int tid)
{
    #pragma unroll
    for (int i = 0; i < 2; i++) {
        int e = tid + i * 256;
        int row = e >> 3, seg = e & 7;
        uint32_t d = dst + (uint32_t)row * BPITCH + (uint32_t)seg * 16u;
        const char* s = (const char*)g_B + ((size_t)row * K_TOT + kk0) * 2 + seg * 16;
        CP_ASYNC16(d, s);
    }
}

// ---------------------------------------------------------------------------
// Main GEMM: out[i][o] += sum_k adj[i][k] * Bt[o][k]  (fp16 MMA, fp32 accum)
// A loads software-pipelined one chunk ahead; RED epilogue onto bias-seeded out.
// Warp tile 16 rows x 64 cols; grid (32, 16), 256 threads.
// ---------------------------------------------------------------------------
__global__ void __launch_bounds__(256, 2) gemm_mma(
    const float* __restrict__ adj, float* __restrict__ out)
{
    __shared__ __align__(16) char sB[2 * BBUF];
    const uint32_t base = smem_u32(sB);

    const int tid  = threadIdx.x;
    const int wid  = tid >> 5;
    const int lane = tid & 31;
    const int g    = lane >> 2;
    const int t    = lane & 3;
    const int i0    = blockIdx.x * TILE_M;
    const int kbase = blockIdx.y * KSPAN;

    float acc[8][4];
    #pragma unroll
    for (int nt = 0; nt < 8; nt++)
        #pragma unroll
        for (int q = 0; q < 4; q++) acc[nt][q] = 0.f;

    const float* ap = adj + (size_t)(i0 + wid * 16 + g) * K_TOT + kbase + 2 * t;

    // prologue: A chunk 0 into registers, B chunk 0 via cp.async
    float2 P[4][4];
    #pragma unroll
    for (int ks = 0; ks < 4; ks++) {
        const float* q0 = ap + ks * 16;
        P[ks][0] = *(const float2*)(q0);
        P[ks][1] = *(const float2*)(q0 + 8 * K_TOT);
        P[ks][2] = *(const float2*)(q0 + 8);
        P[ks][3] = *(const float2*)(q0 + 8 * K_TOT + 8);
    }
    loadB(base, kbase, tid);
    CP_COMMIT();

    const uint32_t lrow = (uint32_t)(lane & 15);
    const uint32_t lkb  = (uint32_t)(lane & 16);

    for (int s = 0; s < NCH; s++) {
        // convert the prefetched A chunk
        uint32_t af[4][4];
        #pragma unroll
        for (int ks = 0; ks < 4; ks++) {
            F16X2(af[ks][0], P[ks][0].x, P[ks][0].y);
            F16X2(af[ks][1], P[ks][1].x, P[ks][1].y);
            F16X2(af[ks][2], P[ks][2].x, P[ks][2].y);
            F16X2(af[ks][3], P[ks][3].x, P[ks][3].y);
        }
        // issue next chunk's A loads (latency hidden behind MMAs below)
        if (s + 1 < NCH) {
            const float* anext = ap + (s + 1) * 64;
            #pragma unroll
            for (int ks = 0; ks < 4; ks++) {
                const float* q0 = anext + ks * 16;
                P[ks][0] = *(const float2*)(q0);
                P[ks][1] = *(const float2*)(q0 + 8 * K_TOT);
                P[ks][2] = *(const float2*)(q0 + 8);
                P[ks][3] = *(const float2*)(q0 + 8 * K_TOT + 8);
            }
        }

        CP_WAIT0();
        __syncthreads();
        if (s + 1 < NCH) {
            loadB(base + (uint32_t)((s + 1) & 1) * BBUF, kbase + (s + 1) * KC, tid);
            CP_COMMIT();
        }
        const uint32_t sb = base + (uint32_t)(s & 1) * BBUF;

        #pragma unroll
        for (int ks = 0; ks < 4; ks++) {
            #pragma unroll
            for (int nt2 = 0; nt2 < 4; nt2++) {
                uint32_t baddr = sb + (uint32_t)(nt2 * 16 + lrow) * BPITCH
                               + (uint32_t)(ks * 32) + lkb;
                uint32_t bb[4];
                LDSM_X4(bb, baddr);
                MMA_F16(acc[nt2 * 2],     af[ks], bb[0], bb[2]);
                MMA_F16(acc[nt2 * 2 + 1], af[ks], bb[1], bb[3]);
            }
        }
    }

    // RED epilogue onto bias-seeded out
    const int r0 = i0 + wid * 16 + g;
    float* p0 = out + (size_t)r0 * 64;
    float* p1 = out + (size_t)(r0 + 8) * 64;
    #pragma unroll
    for (int nt = 0; nt < 8; nt++) {
        const int c0 = nt * 8 + 2 * t;
        atomicAdd(p0 + c0,     acc[nt][0]);
        atomicAdd(p0 + c0 + 1, acc[nt][1]);
        atomicAdd(p1 + c0,     acc[nt][2]);
        atomicAdd(p1 + c0 + 1, acc[nt][3]);
    }
}

// ---------------------------------------------------------------------------
extern "C" void kernel_launch(void* const* d_in, const int* in_sizes, int n_in,
                              void* d_out, int out_size)
{
    const float* features = (const float*)d_in[0];
    const float* adj      = (const float*)d_in[1];
    const float* weight   = (const float*)d_in[2];
    const float* bias     = (const float*)d_in[3];
    float* out            = (float*)d_out;
    (void)in_sizes; (void)n_in; (void)out_size;

    // seed out with bias (graph-capturable async D2D copy)
    cudaMemcpyAsync(out, bias, (size_t)N_NODES * OUT64 * sizeof(float),
                    cudaMemcpyDeviceToDevice);
    build_gemm<<<dim3(32, 4), 256>>>(features, weight);
    gemm_mma<<<dim3(N_NODES / TILE_M, SPLIT), 256>>>(adj, out);
}

// round 10
// speedup vs baseline: 3.7290x; 1.0848x over previous
#include <cuda_runtime.h>
#include <cuda_fp16.h>
#include <cstdint>

#define N_NODES 4096
#define K_TOT   16384
#define OUT64   64

#define TILE_M  128
#define KC      64
#define SPLIT   16
#define KSPAN   (K_TOT / SPLIT)   // 1024
#define NCH     (KSPAN / KC)      // 16

// B^T in fp16: g_B[o][k], 64 x 16384 row-major (o = r*4+kch, k = n*4+c)
__device__ unsigned short g_B[64 * K_TOT];

// ---------------------------------------------------------------------------
__device__ __forceinline__ uint32_t smem_u32(const void* p) {
    uint32_t a;
    asm("{ .reg .u64 t; cvta.to.shared.u64 t, %1; cvt.u32.u64 %0, t; }"
        : "=r"(a) : "l"(p));
    return a;
}

#define CP_ASYNC16(dst, src) \
    asm volatile("cp.async.cg.shared.global [%0], [%1], 16;" :: "r"(dst), "l"(src))
#define CP_COMMIT() asm volatile("cp.async.commit_group;" ::: "memory")
#define CP_WAIT0()  asm volatile("cp.async.wait_group 0;" ::: "memory")

#define LDSM_X4(r, addr) \
    asm volatile("ldmatrix.sync.aligned.m8n8.x4.shared.b16 {%0,%1,%2,%3}, [%4];" \
        : "=r"((r)[0]), "=r"((r)[1]), "=r"((r)[2]), "=r"((r)[3]) : "r"(addr))

#define LDS64F(f0, f1, addr) \
    asm volatile("ld.shared.v2.f32 {%0,%1}, [%2];" : "=f"(f0), "=f"(f1) : "r"(addr))

#define MMA_F16(d, a, b0, b1) \
    asm volatile("mma.sync.aligned.m16n8k16.row.col.f32.f16.f16.f32 " \
        "{%0,%1,%2,%3}, {%4,%5,%6,%7}, {%8,%9}, {%0,%1,%2,%3};" \
        : "+f"((d)[0]), "+f"((d)[1]), "+f"((d)[2]), "+f"((d)[3]) \
        : "r"((a)[0]), "r"((a)[1]), "r"((a)[2]), "r"((a)[3]), "r"(b0), "r"(b1))

// pack two f32 -> f16x2 (x in LOW half, y in HIGH half)
#define F16X2(u, x, y) \
    asm("cvt.rn.f16x2.f32 %0, %1, %2;" : "=r"(u) : "f"(y), "f"(x))

// ---------------------------------------------------------------------------
// build_gemm: g_B^T[n][(o,c)] = features[n,:] @ B2,
//   B2[(j,e)][m=(r,kk,c)] = w[j, r, (kk - c - e) & 3]   (fp16 MMA, K=256)
// ---------------------------------------------------------------------------
#define B2PITCH 528u

__global__ void __launch_bounds__(256) build_gemm(
    const float* __restrict__ features,   // [4096, 256] = [n][(j,e)]
    const float* __restrict__ weight)     // [64, 16, 4]  = [j][r][shift]
{
    __shared__ float s_w[4096];
    __shared__ __align__(16) char s_b2[64 * B2PITCH];

    const int tid  = threadIdx.x;
    const int wid  = tid >> 5;
    const int lane = tid & 31;
    const int g    = lane >> 2;
    const int t    = lane & 3;
    const int n0   = blockIdx.x * 128;
    const int m0   = blockIdx.y * 64;

    #pragma unroll
    for (int i = 0; i < 4; i++)
        ((float4*)s_w)[tid + i * 256] = ((const float4*)weight)[tid + i * 256];
    __syncthreads();

    #pragma unroll
    for (int idx = tid; idx < 64 * 256; idx += 256) {
        const int mloc = idx >> 8, jc = idx & 255;
        const int m = m0 + mloc;
        const int r = m >> 4, kk = (m >> 2) & 3, c = m & 3;
        const int j = jc >> 2, e = jc & 3;
        const float val = s_w[j * 64 + r * 4 + ((kk - c - e) & 3)];
        *(unsigned short*)(s_b2 + mloc * B2PITCH + jc * 2) =
            __half_as_ushort(__float2half_rn(val));
    }
    __syncthreads();

    const uint32_t base = smem_u32(s_b2);
    const uint32_t lrow = (uint32_t)(lane & 15);
    const uint32_t lkb  = (uint32_t)(lane & 16);

    float acc[8][4];
    #pragma unroll
    for (int nt = 0; nt < 8; nt++)
        #pragma unroll
        for (int q = 0; q < 4; q++) acc[nt][q] = 0.f;

    const float* fp = features + (size_t)(n0 + wid * 16 + g) * 256 + 2 * t;

    #pragma unroll 4
    for (int ks = 0; ks < 16; ks++) {
        const float* q0 = fp + ks * 16;
        float2 p0 = *(const float2*)(q0);
        float2 p1 = *(const float2*)(q0 + 8 * 256);
        float2 p2 = *(const float2*)(q0 + 8);
        float2 p3 = *(const float2*)(q0 + 8 * 256 + 8);
        uint32_t af[4];
        F16X2(af[0], p0.x, p0.y);
        F16X2(af[1], p1.x, p1.y);
        F16X2(af[2], p2.x, p2.y);
        F16X2(af[3], p3.x, p3.y);

        #pragma unroll
        for (int nt2 = 0; nt2 < 4; nt2++) {
            uint32_t baddr = base + (uint32_t)(nt2 * 16 + lrow) * B2PITCH
                           + (uint32_t)(ks * 32) + lkb;
            uint32_t bb[4];
            LDSM_X4(bb, baddr);
            MMA_F16(acc[nt2 * 2],     af, bb[0], bb[2]);
            MMA_F16(acc[nt2 * 2 + 1], af, bb[1], bb[3]);
        }
    }

    const int n = n0 + wid * 16 + g;
    #pragma unroll
    for (int nt = 0; nt < 8; nt++) {
        const int m = m0 + nt * 8 + 2 * t;
        const int o = m >> 2, c = m & 3;
        uint32_t lo, hi;
        F16X2(lo, acc[nt][0], acc[nt][1]);
        F16X2(hi, acc[nt][2], acc[nt][3]);
        *(uint32_t*)((char*)g_B + ((size_t)o * K_TOT + n * 4 + c) * 2)       = lo;
        *(uint32_t*)((char*)g_B + ((size_t)o * K_TOT + (n + 8) * 4 + c) * 2) = hi;
    }
}

// ---------------------------------------------------------------------------
// smem layout for main gemm (dynamic):
//   A buffers: 2 x 32768 (128 rows x 256B, XOR-swizzled 16B chunks)
//   B buffers: 2 x 9216  (64 rows x 144B pitch)
// ---------------------------------------------------------------------------
#define ABUF   32768u
#define SM_B0  65536u
#define BPITCH 144u
#define BBUF   9216u
#define SMEM_BYTES (65536 + 18432)

__device__ __forceinline__ void loadA(uint32_t dst, const float* __restrict__ adj,
                                      int i0, int kk0, int tid)
{
    const char* src = (const char*)(adj + (size_t)i0 * K_TOT + kk0);
    #pragma unroll
    for (int i = 0; i < 8; i++) {
        int e = tid + i * 256;               // 2048 16B chunks
        int row = e >> 4, f = e & 15;
        uint32_t d = dst + (uint32_t)row * 256u + (uint32_t)((f ^ (row & 7)) << 4);
        CP_ASYNC16(d, src + (size_t)row * (K_TOT * 4) + f * 16);
    }
}

__device__ __forceinline__ void loadB(uint32_t dst, int kk0, int tid)
{
    #pragma unroll
    for (int i = 0; i < 2; i++) {
        int e = tid + i * 256;
        int row = e >> 3, seg = e & 7;
        uint32_t d = dst + (uint32_t)row * BPITCH + (uint32_t)seg * 16u;
        const char* s = (const char*)g_B + ((size_t)row * K_TOT + kk0) * 2 + seg * 16;
        CP_ASYNC16(d, s);
    }
}

// ---------------------------------------------------------------------------
// Main GEMM: out[i][o] += sum_k adj[i][k] * Bt[o][k]  (fp16 MMA, fp32 accum)
// A staged via cp.async + swizzled smem; RED epilogue onto bias-seeded out.
// Wait discipline: WAIT0 before consuming chunk s (one commit group in
// flight at a time; transfer of s+1 overlaps compute of s).
// ---------------------------------------------------------------------------
__global__ void __launch_bounds__(256, 2) gemm_mma(
    const float* __restrict__ adj, float* __restrict__ out)
{
    extern __shared__ __align__(16) char sm[];
    const uint32_t base = smem_u32(sm);

    const int tid  = threadIdx.x;
    const int wid  = tid >> 5;
    const int lane = tid & 31;
    const int g    = lane >> 2;
    const int t    = lane & 3;
    const int i0    = blockIdx.x * TILE_M;
    const int kbase = blockIdx.y * KSPAN;

    float acc[8][4];
    #pragma unroll
    for (int nt = 0; nt < 8; nt++)
        #pragma unroll
        for (int q = 0; q < 4; q++) acc[nt][q] = 0.f;

    loadA(base, adj, i0, kbase, tid);
    loadB(base + SM_B0, kbase, tid);
    CP_COMMIT();

    const uint32_t lrow = (uint32_t)(lane & 15);
    const uint32_t lkb  = (uint32_t)(lane & 16);
    // per-thread A read base (row wid*16+g, within-chunk (t&1)*8 bytes)
    const uint32_t ar0  = (uint32_t)(wid * 16 + g) * 256u + (uint32_t)((t & 1) << 3);
    const uint32_t xg   = (uint32_t)g << 4;           // swizzle XOR (row&7 == g)
    const uint32_t tch  = (uint32_t)(t >> 1) << 4;    // (t>>1) chunk offset

    for (int s = 0; s < NCH; s++) {
        CP_WAIT0();                // chunk s fully arrived
        __syncthreads();           // all warps done with buffer being refilled
        if (s + 1 < NCH) {
            const int nb = (s + 1) & 1;
            loadA(base + (uint32_t)nb * ABUF, adj, i0, kbase + (s + 1) * KC, tid);
            loadB(base + SM_B0 + (uint32_t)nb * BBUF, kbase + (s + 1) * KC, tid);
            CP_COMMIT();           // transfer overlaps the MMAs below
        }

        const uint32_t sa = base + (uint32_t)(s & 1) * ABUF;
        const uint32_t sb = base + SM_B0 + (uint32_t)(s & 1) * BBUF;

        #pragma unroll
        for (int ks = 0; ks < 4; ks++) {
            // A fragments from swizzled smem: 4 x LDS.64 (2 wavefronts each)
            const uint32_t c0 = ((uint32_t)(ks * 4) << 4) + tch;   // chunk 4ks + t>>1
            const uint32_t c2 = c0 + (2u << 4);                     // +2 chunks (k+8)
            float x0, y0, x1, y1, x2, y2, x3, y3;
            LDS64F(x0, y0, sa + ar0         + (c0 ^ xg));
            LDS64F(x1, y1, sa + ar0 + 2048u + (c0 ^ xg));
            LDS64F(x2, y2, sa + ar0         + (c2 ^ xg));
            LDS64F(x3, y3, sa + ar0 + 2048u + (c2 ^ xg));
            uint32_t af[4];
            F16X2(af[0], x0, y0);
            F16X2(af[1], x1, y1);
            F16X2(af[2], x2, y2);
            F16X2(af[3], x3, y3);

            #pragma unroll
            for (int nt2 = 0; nt2 < 4; nt2++) {
                uint32_t baddr = sb + (uint32_t)(nt2 * 16 + lrow) * BPITCH
                               + (uint32_t)(ks * 32) + lkb;
                uint32_t bb[4];
                LDSM_X4(bb, baddr);
                MMA_F16(acc[nt2 * 2],     af, bb[0], bb[2]);
                MMA_F16(acc[nt2 * 2 + 1], af, bb[1], bb[3]);
            }
        }
    }

    // RED epilogue onto bias-seeded out
    const int r0 = i0 + wid * 16 + g;
    float* p0 = out + (size_t)r0 * 64;
    float* p1 = out + (size_t)(r0 + 8) * 64;
    #pragma unroll
    for (int nt = 0; nt < 8; nt++) {
        const int c0 = nt * 8 + 2 * t;
        atomicAdd(p0 + c0,     acc[nt][0]);
        atomicAdd(p0 + c0 + 1, acc[nt][1]);
        atomicAdd(p1 + c0,     acc[nt][2]);
        atomicAdd(p1 + c0 + 1, acc[nt][3]);
    }
}

// ---------------------------------------------------------------------------
extern "C" void kernel_launch(void* const* d_in, const int* in_sizes, int n_in,
                              void* d_out, int out_size)
{
    const float* features = (const float*)d_in[0];
    const float* adj      = (const float*)d_in[1];
    const float* weight   = (const float*)d_in[2];
    const float* bias     = (const float*)d_in[3];
    float* out            = (float*)d_out;
    (void)in_sizes; (void)n_in; (void)out_size;

    cudaFuncSetAttribute(gemm_mma, cudaFuncAttributeMaxDynamicSharedMemorySize, SMEM_BYTES);

    // seed out with bias (graph-capturable async D2D copy)
    cudaMemcpyAsync(out, bias, (size_t)N_NODES * OUT64 * sizeof(float),
                    cudaMemcpyDeviceToDevice);
    build_gemm<<<dim3(32, 4), 256>>>(features, weight);
    gemm_mma<<<dim3(N_NODES / TILE_M, SPLIT), 256, SMEM_BYTES>>>(adj, out);
}